// round 15
// baseline (speedup 1.0000x reference)
#include <cuda_runtime.h>
#include <math.h>

#define NRES 512
#define CS   384
#define CZ   128
#define NH   12
#define OUTD 2112
#define HF   176
#define PROJW 1152   // 192 q | 192 k | 192 v | 144 qp | 144 kp | 288 vp
#define N2   (NRES*NRES)

// ---------------- scratch ----------------
__device__ alignas(16) float g_proj[NRES*PROJW];
__device__ alignas(16) float g_vg[NRES*288];
__device__ alignas(16) float g_gA[336*NRES];
__device__ alignas(16) float g_gB[336*NRES];
__device__ alignas(16) float g_gC[NH*NRES];
__device__ alignas(16) float g_attn[(size_t)NH*NRES*NRES];   // [h][n][m]
__device__ alignas(16) float g_feats[(size_t)NRES*OUTD];
__device__ alignas(16) float g_part[(size_t)8*NRES*CS];

// ---------------- cp.async helpers ----------------
__device__ __forceinline__ void cpa16(void* dst_smem, const void* src_gmem) {
    unsigned int d = (unsigned int)__cvta_generic_to_shared(dst_smem);
    asm volatile("cp.async.ca.shared.global [%0], [%1], 16;\n" :: "r"(d), "l"(src_gmem));
}
__device__ __forceinline__ void cpa4(void* dst_smem, const void* src_gmem) {
    unsigned int d = (unsigned int)__cvta_generic_to_shared(dst_smem);
    asm volatile("cp.async.ca.shared.global [%0], [%1], 4;\n" :: "r"(d), "l"(src_gmem));
}
#define CP_COMMIT() asm volatile("cp.async.commit_group;\n" ::: "memory")
#define CP_WAIT0()  asm volatile("cp.async.wait_group 0;\n" ::: "memory")
#define CP_WAIT1()  asm volatile("cp.async.wait_group 1;\n" ::: "memory")

// ---------------- fused projection GEMM ----------------
__global__ void k_proj(const float* __restrict__ s,
    const float* __restrict__ Wq,  const float* __restrict__ bq,
    const float* __restrict__ Wk,  const float* __restrict__ bk,
    const float* __restrict__ Wv,  const float* __restrict__ bvs,
    const float* __restrict__ Wqp, const float* __restrict__ bqp,
    const float* __restrict__ Wkp, const float* __restrict__ bkp,
    const float* __restrict__ Wvp, const float* __restrict__ bvp)
{
    __shared__ alignas(16) float As[16][64];
    __shared__ alignas(16) float Bs[16][64];
    const int tid = threadIdx.x;
    const int tx = tid & 15, ty = tid >> 4;
    const int bm = blockIdx.y * 64, bn = blockIdx.x * 64;
    const int am  = tid >> 2, akq = tid & 3;
    const int bkk = tid >> 4, bn4 = tid & 15;

    const int gc = bn + bn4 * 4;
    const float* Bp; int bst;
    if (gc < 576)      { const int sg = gc / 192;
                         const float* Ws = (sg == 0) ? Wq : (sg == 1) ? Wk : Wv;
                         Bp = Ws + (gc - sg * 192); bst = 192; }
    else if (gc < 864) { const int sg = (gc - 576) / 144;
                         Bp = ((sg == 0) ? Wqp : Wkp) + (gc - 576 - sg * 144); bst = 144; }
    else               { Bp = Wvp + (gc - 864); bst = 288; }

    float acc[4][4];
#pragma unroll
    for (int i = 0; i < 4; i++)
#pragma unroll
        for (int j = 0; j < 4; j++) acc[i][j] = 0.f;

    for (int k0 = 0; k0 < CS; k0 += 16) {
        float4 av = *(const float4*)(s + (size_t)(bm + am) * CS + k0 + akq * 4);
        As[akq*4+0][am] = av.x; As[akq*4+1][am] = av.y;
        As[akq*4+2][am] = av.z; As[akq*4+3][am] = av.w;
        float4 wv4 = *(const float4*)(Bp + (size_t)(k0 + bkk) * bst);
        *(float4*)&Bs[bkk][bn4*4] = wv4;
        __syncthreads();
#pragma unroll
        for (int kk = 0; kk < 16; kk++) {
            float4 a = *(const float4*)&As[kk][ty*4];
            float4 b = *(const float4*)&Bs[kk][tx*4];
            acc[0][0]=fmaf(a.x,b.x,acc[0][0]); acc[0][1]=fmaf(a.x,b.y,acc[0][1]);
            acc[0][2]=fmaf(a.x,b.z,acc[0][2]); acc[0][3]=fmaf(a.x,b.w,acc[0][3]);
            acc[1][0]=fmaf(a.y,b.x,acc[1][0]); acc[1][1]=fmaf(a.y,b.y,acc[1][1]);
            acc[1][2]=fmaf(a.y,b.z,acc[1][2]); acc[1][3]=fmaf(a.y,b.w,acc[1][3]);
            acc[2][0]=fmaf(a.z,b.x,acc[2][0]); acc[2][1]=fmaf(a.z,b.y,acc[2][1]);
            acc[2][2]=fmaf(a.z,b.z,acc[2][2]); acc[2][3]=fmaf(a.z,b.w,acc[2][3]);
            acc[3][0]=fmaf(a.w,b.x,acc[3][0]); acc[3][1]=fmaf(a.w,b.y,acc[3][1]);
            acc[3][2]=fmaf(a.w,b.z,acc[3][2]); acc[3][3]=fmaf(a.w,b.w,acc[3][3]);
        }
        __syncthreads();
    }
    const int gc0 = bn + tx * 4;
    const float* bptr;
    if (gc0 < 576)      { const int sg = gc0 / 192;
                          bptr = ((sg == 0) ? bq : (sg == 1) ? bk : bvs) + (gc0 - sg * 192); }
    else if (gc0 < 864) { const int sg = (gc0 - 576) / 144;
                          bptr = ((sg == 0) ? bqp : bkp) + (gc0 - 576 - sg * 144); }
    else                { bptr = bvp + (gc0 - 864); }
#pragma unroll
    for (int i = 0; i < 4; i++) {
        const int row = bm + ty * 4 + i;
#pragma unroll
        for (int j = 0; j < 4; j++)
            g_proj[(size_t)row * PROJW + gc0 + j] = acc[i][j] + bptr[j];
    }
}

// ---------------- prep: frames + GEMM operands A/B/C ----------------
__global__ void k_prep(const float* __restrict__ rot, const float* __restrict__ trans,
                       const float* __restrict__ hw)
{
    const int n = blockIdx.x;
    __shared__ float R[9], T[3];
    __shared__ float kgs[144];
    if (threadIdx.x < 9) R[threadIdx.x] = rot[n*9 + threadIdx.x];
    if (threadIdx.x < 3) T[threadIdx.x] = trans[n*3 + threadIdx.x];
    __syncthreads();
    const int t = threadIdx.x;  // 0..191
    const float* row = g_proj + (size_t)n * PROJW;
    if (t < 48) {
        const float* src = row + 576 + t*3;
        const float p0 = src[0], p1 = src[1], p2 = src[2];
        const float gx = fmaf(R[0],p0, fmaf(R[1],p1, fmaf(R[2],p2, T[0])));
        const float gy = fmaf(R[3],p0, fmaf(R[4],p1, fmaf(R[5],p2, T[1])));
        const float gz = fmaf(R[6],p0, fmaf(R[7],p1, fmaf(R[8],p2, T[2])));
        const int h = t >> 2, p = t & 3;
        const float w = hw[h];
        g_gA[(h*28+16+p*3+0)*NRES + n] = w*gx;
        g_gA[(h*28+16+p*3+1)*NRES + n] = w*gy;
        g_gA[(h*28+16+p*3+2)*NRES + n] = w*gz;
    } else if (t < 96) {
        const int u = t - 48;
        const float* src = row + 720 + u*3;
        const float p0 = src[0], p1 = src[1], p2 = src[2];
        const float gx = fmaf(R[0],p0, fmaf(R[1],p1, fmaf(R[2],p2, T[0])));
        const float gy = fmaf(R[3],p0, fmaf(R[4],p1, fmaf(R[5],p2, T[1])));
        const float gz = fmaf(R[6],p0, fmaf(R[7],p1, fmaf(R[8],p2, T[2])));
        const int h = u >> 2, p = u & 3;
        g_gB[(h*28+16+p*3+0)*NRES + n] = gx;
        g_gB[(h*28+16+p*3+1)*NRES + n] = gy;
        g_gB[(h*28+16+p*3+2)*NRES + n] = gz;
        kgs[u*3+0] = gx; kgs[u*3+1] = gy; kgs[u*3+2] = gz;
    } else {
        const int u = t - 96;
        const float* src = row + 864 + u*3;
        float* dst = g_vg + n*288 + u*3;
        const float p0 = src[0], p1 = src[1], p2 = src[2];
        dst[0] = fmaf(R[0],p0, fmaf(R[1],p1, fmaf(R[2],p2, T[0])));
        dst[1] = fmaf(R[3],p0, fmaf(R[4],p1, fmaf(R[5],p2, T[1])));
        dst[2] = fmaf(R[6],p0, fmaf(R[7],p1, fmaf(R[8],p2, T[2])));
    }
    {
        const int h = t >> 4, c = t & 15;
        g_gA[(h*28+c)*NRES + n] = 0.25f * row[h*16 + c];
        g_gB[(h*28+c)*NRES + n] = row[192 + h*16 + c];
    }
    __syncthreads();
    if (t < 12) {
        float s2 = 0.f;
#pragma unroll
        for (int j = 0; j < 12; j++) s2 = fmaf(kgs[t*12+j], kgs[t*12+j], s2);
        g_gC[t*NRES + n] = -0.5f * hw[t] * s2;
    }
}

// ---------------- pair bias stream: 2 head-groups x 6 heads, c-split pairs ----------------
#define PB_WBT 0        // 1536
#define PB_EMB 1536     // 768
#define PB_PH  2304     // 36
#define PB_BB  2340     // 12
#define PB_TN  2352     // 4
#define PB_TM0 2356     // 192
#define PB_TM1 2548     // 192
#define PB_RED 2740     // 768
#define PB_Z0  3508     // 8448
#define PB_Z1  11956    // 8448
#define PB_END 20404    // 81616 B
__global__ void k_pairbias(const float* __restrict__ z, const float* __restrict__ trans,
                           const float* __restrict__ Wb, const float* __restrict__ bb,
                           const float* __restrict__ emb, const float* __restrict__ sl)
{
    extern __shared__ float sm[];
    const int n = blockIdx.x, tid = threadIdx.x;  // 256 thr

    auto pf = [&](int buf, int mc) {
        const float4* zsrc = (const float4*)(z + ((size_t)n * NRES + mc*64) * CZ);
        float* zb = sm + (buf ? PB_Z1 : PB_Z0);
        for (int i = tid; i < 2048; i += 256)
            cpa16(zb + (i >> 5)*132 + (i & 31)*4, zsrc + i);
        if (tid < 48)
            cpa16(sm + (buf ? PB_TM1 : PB_TM0) + tid*4, trans + mc*192 + tid*4);
    };
    pf(0, 0); CP_COMMIT();
    pf(1, 1); CP_COMMIT();

    for (int i = tid; i < 1536; i += 256) {
        const int h = i >> 7, c = i & 127;
        sm[PB_WBT + i] = Wb[c*NH + h];
    }
    for (int i = tid; i < 768; i += 256) sm[PB_EMB + i] = emb[i];
    if (tid < 12) {
        sm[PB_BB + tid] = bb[tid];
        const float e0 = expf(sl[tid]), e1 = expf(sl[12+tid]), e2 = expf(sl[24+tid]);
        const float inv = 1.0f / (e0 + e1 + e2);
        sm[PB_PH + tid] = e0*inv; sm[PB_PH + 12 + tid] = e1*inv; sm[PB_PH + 24 + tid] = e2*inv;
    }
    if (tid < 3) sm[PB_TN + tid] = trans[n*3 + tid];

    const int hg = tid >> 7;            // 0..1 (6 heads each)
    const int cs = (tid >> 6) & 1;      // c4 split
    const int ml = tid & 63;
    const int hb = hg * 6;

    for (int mc = 0; mc < 8; mc++) {
        if (mc < 7) CP_WAIT1(); else CP_WAIT0();
        __syncthreads();
        const int buf = mc & 1;
        const float4* zr = (const float4*)(sm + (buf ? PB_Z1 : PB_Z0) + ml*132) + cs*16;
        const float* tm = sm + (buf ? PB_TM1 : PB_TM0);

        float a[6][4];
#pragma unroll
        for (int j = 0; j < 6; j++) { a[j][0]=0.f; a[j][1]=0.f; a[j][2]=0.f; a[j][3]=0.f; }
#pragma unroll 4
        for (int c4 = 0; c4 < 16; c4++) {
            const float4 zv = zr[c4];
#pragma unroll
            for (int j = 0; j < 6; j++) {
                const float4 w = ((const float4*)(sm + PB_WBT + (hb+j)*128))[cs*16 + c4];
                a[j][0] = fmaf(zv.x, w.x, a[j][0]);
                a[j][1] = fmaf(zv.y, w.y, a[j][1]);
                a[j][2] = fmaf(zv.z, w.z, a[j][2]);
                a[j][3] = fmaf(zv.w, w.w, a[j][3]);
            }
        }
        float p[6];
#pragma unroll
        for (int j = 0; j < 6; j++) p[j] = (a[j][0]+a[j][1]) + (a[j][2]+a[j][3]);
        if (cs == 1) {
#pragma unroll
            for (int j = 0; j < 6; j++) sm[PB_RED + hg*384 + ml*6 + j] = p[j];
        }
        __syncthreads();
        if (cs == 0) {
            const float dx = sm[PB_TN+0] - tm[ml*3+0];
            const float dy = sm[PB_TN+1] - tm[ml*3+1];
            const float dz = sm[PB_TN+2] - tm[ml*3+2];
            const float dist = __fsqrt_rn(fmaf(dx,dx, fmaf(dy,dy, dz*dz)));
            int bin = (int)ceilf(dist * 2.0f) - 1;
            bin = max(0, min(63, bin));
            const int msrow = (dist <= 5.0f) ? 0 : (dist <= 15.0f) ? 12 : -1;
            const int m = mc*64 + ml;
#pragma unroll
            for (int j = 0; j < 6; j++) {
                const int h = hb + j;
                float v = sm[PB_BB + h] + p[j] + sm[PB_RED + hg*384 + ml*6 + j];
                v += sm[PB_EMB + bin*12 + h] + sm[PB_PH + 24 + h];
                if (msrow >= 0) v += sm[PB_PH + msrow + h];
                g_attn[(size_t)h*N2 + (size_t)n*NRES + m] = v;
            }
        }
        __syncthreads();
        if (mc + 2 < 8) { pf(buf, mc + 2); CP_COMMIT(); }
    }
}

// ---------------- fused geometry GEMM + softmax ----------------
// block = (16 n, 1 head, all m=512); thread = (n-local, m-group of 32)
#define GS_A 0        // 28*16 = 448
#define GS_C 448      // 512
#define GS_B 960      // 28*512 = 14336
#define GS_END 15296  // 61184 B
__global__ void k_geosm()
{
    extern __shared__ float sm[];
    const int h = blockIdx.y;
    const int n0 = blockIdx.x * 16;
    const int tid = threadIdx.x;      // 256
    const int nl = tid >> 4, mg = tid & 15;

    for (int i = tid; i < 448; i += 256) {
        const int c = i >> 4, r = i & 15;
        sm[GS_A + c*16 + r] = g_gA[(size_t)(h*28+c)*NRES + n0 + r];
    }
    for (int i = tid; i < 128; i += 256)
        *(float4*)(sm + GS_C + i*4) = *(const float4*)(g_gC + h*NRES + i*4);
    for (int i = tid; i < 3584; i += 256) {
        const int c = i >> 7, mq = i & 127;
        *(float4*)(sm + GS_B + c*512 + mq*4) =
            *(const float4*)(g_gB + (size_t)(h*28+c)*NRES + mq*4);
    }
    __syncthreads();

    float acc[32];
#pragma unroll
    for (int j = 0; j < 32; j++) acc[j] = 0.f;

#pragma unroll 4
    for (int c = 0; c < 28; c++) {
        const float a = sm[GS_A + c*16 + nl];
        const float4* b4 = (const float4*)(sm + GS_B + c*512) + mg*8;
#pragma unroll
        for (int j = 0; j < 8; j++) {
            const float4 b = b4[j];
            acc[j*4+0] = fmaf(a, b.x, acc[j*4+0]);
            acc[j*4+1] = fmaf(a, b.y, acc[j*4+1]);
            acc[j*4+2] = fmaf(a, b.z, acc[j*4+2]);
            acc[j*4+3] = fmaf(a, b.w, acc[j*4+3]);
        }
    }

    float4* arow = (float4*)(g_attn + (size_t)h*N2 + (size_t)(n0+nl)*NRES + mg*32);
    const float4* cv4 = (const float4*)(sm + GS_C + mg*32);
    float mx = -1e30f;
#pragma unroll
    for (int j = 0; j < 8; j++) {
        const float4 bias = arow[j];
        const float4 cv = cv4[j];
        acc[j*4+0] += bias.x + cv.x;
        acc[j*4+1] += bias.y + cv.y;
        acc[j*4+2] += bias.z + cv.z;
        acc[j*4+3] += bias.w + cv.w;
        mx = fmaxf(mx, fmaxf(fmaxf(acc[j*4+0], acc[j*4+1]), fmaxf(acc[j*4+2], acc[j*4+3])));
    }
    // same-n threads form one 16-lane half-warp (lane = (nl&1)*16 + mg)
#pragma unroll
    for (int o = 8; o; o >>= 1) mx = fmaxf(mx, __shfl_xor_sync(0xffffffffu, mx, o));
    float sum = 0.f;
#pragma unroll
    for (int j = 0; j < 32; j++) { acc[j] = __expf(acc[j] - mx); sum += acc[j]; }
#pragma unroll
    for (int o = 8; o; o >>= 1) sum += __shfl_xor_sync(0xffffffffu, sum, o);
    const float inv = 1.0f / sum;
#pragma unroll
    for (int j = 0; j < 8; j++)
        arow[j] = make_float4(acc[j*4+0]*inv, acc[j*4+1]*inv, acc[j*4+2]*inv, acc[j*4+3]*inv);
}

// ---------------- pair_feat: warp = (head-group of 4, m-slice), 1 z-LDS per 16 FMA ----
#define PF_Z0 0       // 4096
#define PF_Z1 4096    // 4096
#define PF_A0 8192    // 384
#define PF_A1 8576    // 384
#define PF_PF 8960    // 1536
#define PF_END 10496  // 41984 B
__global__ void k_pairfeat(const float* __restrict__ z)
{
    extern __shared__ float sm[];
    const int n = blockIdx.x, tid = threadIdx.x;  // 384 thr = 12 warps
    const int wid = tid >> 5, lane = tid & 31;
    const int hg = wid >> 2;          // 0..2 (4 heads each)
    const int ms = wid & 3;           // m-slice

    const float4* zsrc = (const float4*)(z + (size_t)n * NRES * CZ);

    auto pfl = [&](int buf, int mc) {
        float* zb = sm + (buf ? PF_Z1 : PF_Z0);
        for (int i = tid; i < 1024; i += 384)
            cpa16(zb + i*4, zsrc + mc*1024 + i);
        {
            const int h = tid >> 5, mm = tid & 31;
            cpa4(sm + (buf ? PF_A1 : PF_A0) + h*32 + mm,
                 g_attn + (size_t)h*N2 + (size_t)n*NRES + mc*32 + mm);
        }
    };
    pfl(0, 0); CP_COMMIT();
    pfl(1, 1); CP_COMMIT();

    float acc[4][4];
#pragma unroll
    for (int i = 0; i < 4; i++)
#pragma unroll
        for (int j = 0; j < 4; j++) acc[i][j] = 0.f;

    for (int mc = 0; mc < 16; mc++) {
        if (mc < 15) CP_WAIT1(); else CP_WAIT0();
        __syncthreads();
        const int buf = mc & 1;
        const float* zc = sm + (buf ? PF_Z1 : PF_Z0);
        const float* ac = sm + (buf ? PF_A1 : PF_A0);
#pragma unroll
        for (int j = 0; j < 8; j++) {
            const int m = ms*8 + j;
            const float4 zv = *(const float4*)(zc + m*128 + lane*4);
            const float w0 = ac[(hg*4+0)*32 + m];
            const float w1 = ac[(hg*4+1)*32 + m];
            const float w2 = ac[(hg*4+2)*32 + m];
            const float w3 = ac[(hg*4+3)*32 + m];
            acc[0][0]=fmaf(w0,zv.x,acc[0][0]); acc[0][1]=fmaf(w0,zv.y,acc[0][1]);
            acc[0][2]=fmaf(w0,zv.z,acc[0][2]); acc[0][3]=fmaf(w0,zv.w,acc[0][3]);
            acc[1][0]=fmaf(w1,zv.x,acc[1][0]); acc[1][1]=fmaf(w1,zv.y,acc[1][1]);
            acc[1][2]=fmaf(w1,zv.z,acc[1][2]); acc[1][3]=fmaf(w1,zv.w,acc[1][3]);
            acc[2][0]=fmaf(w2,zv.x,acc[2][0]); acc[2][1]=fmaf(w2,zv.y,acc[2][1]);
            acc[2][2]=fmaf(w2,zv.z,acc[2][2]); acc[2][3]=fmaf(w2,zv.w,acc[2][3]);
            acc[3][0]=fmaf(w3,zv.x,acc[3][0]); acc[3][1]=fmaf(w3,zv.y,acc[3][1]);
            acc[3][2]=fmaf(w3,zv.z,acc[3][2]); acc[3][3]=fmaf(w3,zv.w,acc[3][3]);
        }
        __syncthreads();
        if (mc + 2 < 16) { pfl(buf, mc + 2); CP_COMMIT(); }
    }

    float4* pf4 = (float4*)(sm + PF_PF);
#pragma unroll
    for (int r = 0; r < 4; r++) {
        if (ms == r) {
#pragma unroll
            for (int hh = 0; hh < 4; hh++) {
                const int fi = (hg*4 + hh)*32 + lane;
                if (r == 0) {
                    pf4[fi] = make_float4(acc[hh][0], acc[hh][1], acc[hh][2], acc[hh][3]);
                } else {
                    float4 v = pf4[fi];
                    v.x += acc[hh][0]; v.y += acc[hh][1];
                    v.z += acc[hh][2]; v.w += acc[hh][3];
                    pf4[fi] = v;
                }
            }
        }
        __syncthreads();
    }
    {
        const int h = tid >> 5, cq = tid & 31;
        *(float4*)(g_feats + (size_t)n*OUTD + h*HF + 48 + cq*4) = pf4[tid];
    }
}

// ---------------- out_scalar + out_pts(local) + norms; 4 n per block ----------------
#define OV_AT 0        // 12*128 [h][m][ni]
#define OV_V  1536     // 6144
#define OV_VG 7680     // 9216
#define OV_PG 16896    // 4*288
#define OV_END 18048
__global__ void k_outv(const float* __restrict__ rot, const float* __restrict__ trans)
{
    extern __shared__ float sm[];
    const int n0 = blockIdx.x * 4, tid = threadIdx.x;  // 480 thr, grid 128
    float acc0=0.f, acc1=0.f, acc2=0.f, acc3=0.f;

    for (int mc = 0; mc < 16; mc++) {
        const int m0 = mc * 32;
        __syncthreads();
        for (int i = tid; i < 1536; i += 480) {
            const int hh = i >> 7, r = i & 127;
            const int ni = r >> 5, mm = r & 31;
            sm[OV_AT + hh*128 + mm*4 + ni] =
                g_attn[(size_t)hh*N2 + (size_t)(n0+ni)*NRES + m0 + mm];
        }
        for (int i = tid; i < 1536; i += 480) {
            const int mm = i / 48, q = i - mm*48;
            cpa16(sm + OV_V + mm*192 + q*4, g_proj + (size_t)(m0+mm)*PROJW + 384 + q*4);
        }
        for (int i = tid; i < 2304; i += 480)
            cpa16(sm + OV_VG + i*4, g_vg + m0*288 + i*4);
        CP_COMMIT(); CP_WAIT0();
        __syncthreads();

        if (tid < 192) {
            const int hh = tid >> 4, c = tid & 15;
            const float* vs = sm + OV_V + hh*16 + c;
            const float4* at4 = (const float4*)(sm + OV_AT + hh*128);
#pragma unroll
            for (int mm = 0; mm < 32; mm++) {
                const float4 w = at4[mm];
                const float vv = vs[mm*192];
                acc0 = fmaf(w.x, vv, acc0);
                acc1 = fmaf(w.y, vv, acc1);
                acc2 = fmaf(w.z, vv, acc2);
                acc3 = fmaf(w.w, vv, acc3);
            }
        } else {
            const int idx = tid - 192, hh = idx / 24, u = idx - hh*24;
            const float* vs = sm + OV_VG + hh*24 + u;
            const float4* at4 = (const float4*)(sm + OV_AT + hh*128);
#pragma unroll
            for (int mm = 0; mm < 32; mm++) {
                const float4 w = at4[mm];
                const float vv = vs[mm*288];
                acc0 = fmaf(w.x, vv, acc0);
                acc1 = fmaf(w.y, vv, acc1);
                acc2 = fmaf(w.z, vv, acc2);
                acc3 = fmaf(w.w, vv, acc3);
            }
        }
    }
    __syncthreads();
    if (tid < 192) {
        const int hh = tid >> 4, c = tid & 15;
        g_feats[(size_t)(n0+0)*OUTD + hh*HF + c] = acc0;
        g_feats[(size_t)(n0+1)*OUTD + hh*HF + c] = acc1;
        g_feats[(size_t)(n0+2)*OUTD + hh*HF + c] = acc2;
        g_feats[(size_t)(n0+3)*OUTD + hh*HF + c] = acc3;
    } else {
        const int idx = tid - 192;
        sm[OV_PG + 0*288 + idx] = acc0;
        sm[OV_PG + 1*288 + idx] = acc1;
        sm[OV_PG + 2*288 + idx] = acc2;
        sm[OV_PG + 3*288 + idx] = acc3;
    }
    __syncthreads();
    if (tid < 384) {
        const int ni = tid / 96, r = tid - ni*96;
        const int hh = r / 8, p = r - hh*8;
        const int n = n0 + ni;
        float R[9];
#pragma unroll
        for (int i = 0; i < 9; i++) R[i] = rot[n*9 + i];
        const float gx = sm[OV_PG + ni*288 + hh*24 + p*3 + 0] - trans[n*3 + 0];
        const float gy = sm[OV_PG + ni*288 + hh*24 + p*3 + 1] - trans[n*3 + 1];
        const float gz = sm[OV_PG + ni*288 + hh*24 + p*3 + 2] - trans[n*3 + 2];
        const float lx = fmaf(R[0],gx, fmaf(R[3],gy, R[6]*gz));
        const float ly = fmaf(R[1],gx, fmaf(R[4],gy, R[7]*gz));
        const float lz = fmaf(R[2],gx, fmaf(R[5],gy, R[8]*gz));
        float* f = g_feats + (size_t)n*OUTD + hh*HF;
        f[16 + p*3 + 0] = lx; f[16 + p*3 + 1] = ly; f[16 + p*3 + 2] = lz;
        f[40 + p] = __fsqrt_rn(fmaf(lx,lx, fmaf(ly,ly, lz*lz)));
    }
}

// ---------------- selective-K GEMM over per-head column ranges (+row base) ------
__global__ void k_sgemm_sel(const float* __restrict__ A, const float* __restrict__ B,
                            float* __restrict__ C, int pbase, int kbase, int klen, int mbase)
{
    __shared__ alignas(16) float As[16][64];
    __shared__ alignas(16) float Bs[16][64];
    const int tid = threadIdx.x;
    const int tx = tid & 15, ty = tid >> 4;
    const int bm = (mbase + blockIdx.y) * 64, bn = blockIdx.x * 64;
    const int hb = blockIdx.z * 3;
    C += (size_t)(pbase + blockIdx.z) * NRES * CS;

    const int am  = tid >> 2, akq = tid & 3;
    const int bkk = tid >> 4, bn4 = tid & 15;

    float acc[4][4];
#pragma unroll
    for (int i = 0; i < 4; i++)
#pragma unroll
        for (int j = 0; j < 4; j++) acc[i][j] = 0.f;

    for (int hh = hb; hh < hb + 3; hh++) {
        const int kc0 = hh * HF + kbase;
        for (int kt = 0; kt < klen; kt += 16) {
            const int kc = kc0 + kt;
            float4 av = *(const float4*)(A + (size_t)(bm + am) * OUTD + kc + akq * 4);
            As[akq*4+0][am] = av.x; As[akq*4+1][am] = av.y;
            As[akq*4+2][am] = av.z; As[akq*4+3][am] = av.w;
            float4 bv = *(const float4*)(B + (size_t)(kc + bkk) * CS + bn + bn4 * 4);
            *(float4*)&Bs[bkk][bn4*4] = bv;
            __syncthreads();
#pragma unroll
            for (int kk = 0; kk < 16; kk++) {
                float4 a = *(const float4*)&As[kk][ty*4];
                float4 b = *(const float4*)&Bs[kk][tx*4];
                acc[0][0]=fmaf(a.x,b.x,acc[0][0]); acc[0][1]=fmaf(a.x,b.y,acc[0][1]);
                acc[0][2]=fmaf(a.x,b.z,acc[0][2]); acc[0][3]=fmaf(a.x,b.w,acc[0][3]);
                acc[1][0]=fmaf(a.y,b.x,acc[1][0]); acc[1][1]=fmaf(a.y,b.y,acc[1][1]);
                acc[1][2]=fmaf(a.y,b.z,acc[1][2]); acc[1][3]=fmaf(a.y,b.w,acc[1][3]);
                acc[2][0]=fmaf(a.z,b.x,acc[2][0]); acc[2][1]=fmaf(a.z,b.y,acc[2][1]);
                acc[2][2]=fmaf(a.z,b.z,acc[2][2]); acc[2][3]=fmaf(a.z,b.w,acc[2][3]);
                acc[3][0]=fmaf(a.w,b.x,acc[3][0]); acc[3][1]=fmaf(a.w,b.y,acc[3][1]);
                acc[3][2]=fmaf(a.w,b.z,acc[3][2]); acc[3][3]=fmaf(a.w,b.w,acc[3][3]);
            }
            __syncthreads();
        }
    }
#pragma unroll
    for (int i = 0; i < 4; i++) {
        const int row = bm + ty * 4 + i;
#pragma unroll
        for (int j = 0; j < 4; j++)
            C[(size_t)row * CS + bn + tx * 4 + j] = acc[i][j];
    }
}

// ---------------- reduce 8 partials + bias ----------------
__global__ void k_reduce(const float* __restrict__ bout, float* __restrict__ out)
{
    const int i = blockIdx.x * 256 + threadIdx.x;
    const int NE = NRES * CS;
    float v = 0.f;
#pragma unroll
    for (int p = 0; p < 8; p++) v += g_part[(size_t)p*NE + i];
    out[i] = v + bout[i % CS];
}

// ---------------- launch ----------------
static float* symaddr(const void* sym) {
    void* p = nullptr;
    cudaGetSymbolAddress(&p, sym);
    return (float*)p;
}

extern "C" void kernel_launch(void* const* d_in, const int* in_sizes, int n_in,
                              void* d_out, int out_size) {
    const float* s     = (const float*)d_in[0];
    const float* z     = (const float*)d_in[1];
    const float* trans = (const float*)d_in[2];
    const float* rot   = (const float*)d_in[3];
    const float* Wq    = (const float*)d_in[4];
    const float* bq    = (const float*)d_in[5];
    const float* Wk    = (const float*)d_in[6];
    const float* bk    = (const float*)d_in[7];
    const float* Wv    = (const float*)d_in[8];
    const float* bv    = (const float*)d_in[9];
    const float* Wqp   = (const float*)d_in[10];
    const float* bqp   = (const float*)d_in[11];
    const float* Wkp   = (const float*)d_in[12];
    const float* bkp   = (const float*)d_in[13];
    const float* Wvp   = (const float*)d_in[14];
    const float* bvp   = (const float*)d_in[15];
    const float* Wb    = (const float*)d_in[16];
    const float* bb    = (const float*)d_in[17];
    const float* emb   = (const float*)d_in[18];
    const float* sl    = (const float*)d_in[19];
    const float* hw    = (const float*)d_in[20];
    const float* Wout  = (const float*)d_in[21];
    const float* bout  = (const float*)d_in[22];
    float* out = (float*)d_out;

    float* pf = symaddr(g_feats);
    float* pp = symaddr(g_part);

    static cudaStream_t s2 = nullptr;
    static cudaEvent_t evFork = nullptr, evZ = nullptr, evS = nullptr, evPF = nullptr, evP = nullptr;
    if (!s2) {
        cudaStreamCreateWithFlags(&s2, cudaStreamNonBlocking);
        cudaEventCreateWithFlags(&evFork, cudaEventDisableTiming);
        cudaEventCreateWithFlags(&evZ,    cudaEventDisableTiming);
        cudaEventCreateWithFlags(&evS,    cudaEventDisableTiming);
        cudaEventCreateWithFlags(&evPF,   cudaEventDisableTiming);
        cudaEventCreateWithFlags(&evP,    cudaEventDisableTiming);
        cudaFuncSetAttribute(k_pairbias, cudaFuncAttributeMaxDynamicSharedMemorySize, PB_END * (int)sizeof(float));
        cudaFuncSetAttribute(k_geosm,    cudaFuncAttributeMaxDynamicSharedMemorySize, GS_END * (int)sizeof(float));
        cudaFuncSetAttribute(k_pairfeat, cudaFuncAttributeMaxDynamicSharedMemorySize, PF_END * (int)sizeof(float));
        cudaFuncSetAttribute(k_outv,     cudaFuncAttributeMaxDynamicSharedMemorySize, OV_END * (int)sizeof(float));
    }

    // fork1: z-path (pairbias) on s2 concurrent with s-path (proj->prep) on default
    cudaEventRecord(evFork, 0);
    cudaStreamWaitEvent(s2, evFork, 0);
    k_pairbias<<<NRES, 256, PB_END * sizeof(float), s2>>>(z, trans, Wb, bb, emb, sl);
    cudaEventRecord(evZ, s2);

    k_proj<<<dim3(18,8,1), 256>>>(s, Wq,bq, Wk,bk, Wv,bv, Wqp,bqp, Wkp,bkp, Wvp,bvp);
    k_prep<<<NRES, 192>>>(rot, trans, hw);

    // join: geosm RMWs attn (needs pairbias) and reads prep outputs; includes softmax
    cudaStreamWaitEvent(0, evZ, 0);
    k_geosm<<<dim3(32,12,1), 256, GS_END * sizeof(float)>>>();
    cudaEventRecord(evS, 0);

    // fork2: pairfeat + 6/8 of gemmB on s2; outv + gemmA + 2/8 of gemmB on default
    cudaStreamWaitEvent(s2, evS, 0);
    k_pairfeat<<<NRES, 384, PF_END * sizeof(float), s2>>>(z);
    cudaEventRecord(evPF, s2);
    k_sgemm_sel<<<dim3(6,6,4), 256, 0, s2>>>(pf, Wout, pp, 4, 48, 128, 0);  // rows 0-5
    cudaEventRecord(evP, s2);

    k_outv<<<128, 480, OV_END * sizeof(float)>>>(rot, trans);
    k_sgemm_sel<<<dim3(6,8,4), 256>>>(pf, Wout, pp, 0, 0, 48, 0);           // gemmA
    cudaStreamWaitEvent(0, evPF, 0);
    k_sgemm_sel<<<dim3(6,2,4), 256>>>(pf, Wout, pp, 4, 48, 128, 6);         // rows 6-7

    // join before reduce (needs all 8 partials)
    cudaStreamWaitEvent(0, evP, 0);
    k_reduce<<<(NRES*CS)/256, 256>>>(bout, out);
}

// round 17
// speedup vs baseline: 1.2232x; 1.2232x over previous
#include <cuda_runtime.h>
#include <math.h>

#define NRES 512
#define CS   384
#define CZ   128
#define NH   12
#define OUTD 2112
#define HF   176
#define PROJW 1152   // 192 q | 192 k | 192 v | 144 qp | 144 kp | 288 vp
#define N2   (NRES*NRES)

// ---------------- scratch ----------------
__device__ alignas(16) float g_proj[NRES*PROJW];
__device__ alignas(16) float g_vg[NRES*288];
__device__ alignas(16) float g_gA[336*NRES];
__device__ alignas(16) float g_gB[336*NRES];
__device__ alignas(16) float g_gC[NH*NRES];
__device__ alignas(16) float g_attn[(size_t)NH*NRES*NRES];   // [h][n][m]
__device__ alignas(16) float g_feats[(size_t)NRES*OUTD];
__device__ alignas(16) float g_part[(size_t)8*NRES*CS];

// ---------------- cp.async helpers ----------------
__device__ __forceinline__ void cpa16(void* dst_smem, const void* src_gmem) {
    unsigned int d = (unsigned int)__cvta_generic_to_shared(dst_smem);
    asm volatile("cp.async.ca.shared.global [%0], [%1], 16;\n" :: "r"(d), "l"(src_gmem));
}
__device__ __forceinline__ void cpa4(void* dst_smem, const void* src_gmem) {
    unsigned int d = (unsigned int)__cvta_generic_to_shared(dst_smem);
    asm volatile("cp.async.ca.shared.global [%0], [%1], 4;\n" :: "r"(d), "l"(src_gmem));
}
#define CP_COMMIT() asm volatile("cp.async.commit_group;\n" ::: "memory")
#define CP_WAIT0()  asm volatile("cp.async.wait_group 0;\n" ::: "memory")
#define CP_WAIT1()  asm volatile("cp.async.wait_group 1;\n" ::: "memory")

// ---------------- fused projection GEMM ----------------
__global__ void k_proj(const float* __restrict__ s,
    const float* __restrict__ Wq,  const float* __restrict__ bq,
    const float* __restrict__ Wk,  const float* __restrict__ bk,
    const float* __restrict__ Wv,  const float* __restrict__ bvs,
    const float* __restrict__ Wqp, const float* __restrict__ bqp,
    const float* __restrict__ Wkp, const float* __restrict__ bkp,
    const float* __restrict__ Wvp, const float* __restrict__ bvp)
{
    __shared__ alignas(16) float As[16][64];
    __shared__ alignas(16) float Bs[16][64];
    const int tid = threadIdx.x;
    const int tx = tid & 15, ty = tid >> 4;
    const int bm = blockIdx.y * 64, bn = blockIdx.x * 64;
    const int am  = tid >> 2, akq = tid & 3;
    const int bkk = tid >> 4, bn4 = tid & 15;

    const int gc = bn + bn4 * 4;
    const float* Bp; int bst;
    if (gc < 576)      { const int sg = gc / 192;
                         const float* Ws = (sg == 0) ? Wq : (sg == 1) ? Wk : Wv;
                         Bp = Ws + (gc - sg * 192); bst = 192; }
    else if (gc < 864) { const int sg = (gc - 576) / 144;
                         Bp = ((sg == 0) ? Wqp : Wkp) + (gc - 576 - sg * 144); bst = 144; }
    else               { Bp = Wvp + (gc - 864); bst = 288; }

    float acc[4][4];
#pragma unroll
    for (int i = 0; i < 4; i++)
#pragma unroll
        for (int j = 0; j < 4; j++) acc[i][j] = 0.f;

    for (int k0 = 0; k0 < CS; k0 += 16) {
        float4 av = *(const float4*)(s + (size_t)(bm + am) * CS + k0 + akq * 4);
        As[akq*4+0][am] = av.x; As[akq*4+1][am] = av.y;
        As[akq*4+2][am] = av.z; As[akq*4+3][am] = av.w;
        float4 wv4 = *(const float4*)(Bp + (size_t)(k0 + bkk) * bst);
        *(float4*)&Bs[bkk][bn4*4] = wv4;
        __syncthreads();
#pragma unroll
        for (int kk = 0; kk < 16; kk++) {
            float4 a = *(const float4*)&As[kk][ty*4];
            float4 b = *(const float4*)&Bs[kk][tx*4];
            acc[0][0]=fmaf(a.x,b.x,acc[0][0]); acc[0][1]=fmaf(a.x,b.y,acc[0][1]);
            acc[0][2]=fmaf(a.x,b.z,acc[0][2]); acc[0][3]=fmaf(a.x,b.w,acc[0][3]);
            acc[1][0]=fmaf(a.y,b.x,acc[1][0]); acc[1][1]=fmaf(a.y,b.y,acc[1][1]);
            acc[1][2]=fmaf(a.y,b.z,acc[1][2]); acc[1][3]=fmaf(a.y,b.w,acc[1][3]);
            acc[2][0]=fmaf(a.z,b.x,acc[2][0]); acc[2][1]=fmaf(a.z,b.y,acc[2][1]);
            acc[2][2]=fmaf(a.z,b.z,acc[2][2]); acc[2][3]=fmaf(a.z,b.w,acc[2][3]);
            acc[3][0]=fmaf(a.w,b.x,acc[3][0]); acc[3][1]=fmaf(a.w,b.y,acc[3][1]);
            acc[3][2]=fmaf(a.w,b.z,acc[3][2]); acc[3][3]=fmaf(a.w,b.w,acc[3][3]);
        }
        __syncthreads();
    }
    const int gc0 = bn + tx * 4;
    const float* bptr;
    if (gc0 < 576)      { const int sg = gc0 / 192;
                          bptr = ((sg == 0) ? bq : (sg == 1) ? bk : bvs) + (gc0 - sg * 192); }
    else if (gc0 < 864) { const int sg = (gc0 - 576) / 144;
                          bptr = ((sg == 0) ? bqp : bkp) + (gc0 - 576 - sg * 144); }
    else                { bptr = bvp + (gc0 - 864); }
#pragma unroll
    for (int i = 0; i < 4; i++) {
        const int row = bm + ty * 4 + i;
#pragma unroll
        for (int j = 0; j < 4; j++)
            g_proj[(size_t)row * PROJW + gc0 + j] = acc[i][j] + bptr[j];
    }
}

// ---------------- prep: frames + GEMM operands A/B/C ----------------
__global__ void k_prep(const float* __restrict__ rot, const float* __restrict__ trans,
                       const float* __restrict__ hw)
{
    const int n = blockIdx.x;
    __shared__ float R[9], T[3];
    __shared__ float kgs[144];
    if (threadIdx.x < 9) R[threadIdx.x] = rot[n*9 + threadIdx.x];
    if (threadIdx.x < 3) T[threadIdx.x] = trans[n*3 + threadIdx.x];
    __syncthreads();
    const int t = threadIdx.x;  // 0..191
    const float* row = g_proj + (size_t)n * PROJW;
    if (t < 48) {
        const float* src = row + 576 + t*3;
        const float p0 = src[0], p1 = src[1], p2 = src[2];
        const float gx = fmaf(R[0],p0, fmaf(R[1],p1, fmaf(R[2],p2, T[0])));
        const float gy = fmaf(R[3],p0, fmaf(R[4],p1, fmaf(R[5],p2, T[1])));
        const float gz = fmaf(R[6],p0, fmaf(R[7],p1, fmaf(R[8],p2, T[2])));
        const int h = t >> 2, p = t & 3;
        const float w = hw[h];
        g_gA[(h*28+16+p*3+0)*NRES + n] = w*gx;
        g_gA[(h*28+16+p*3+1)*NRES + n] = w*gy;
        g_gA[(h*28+16+p*3+2)*NRES + n] = w*gz;
    } else if (t < 96) {
        const int u = t - 48;
        const float* src = row + 720 + u*3;
        const float p0 = src[0], p1 = src[1], p2 = src[2];
        const float gx = fmaf(R[0],p0, fmaf(R[1],p1, fmaf(R[2],p2, T[0])));
        const float gy = fmaf(R[3],p0, fmaf(R[4],p1, fmaf(R[5],p2, T[1])));
        const float gz = fmaf(R[6],p0, fmaf(R[7],p1, fmaf(R[8],p2, T[2])));
        const int h = u >> 2, p = u & 3;
        g_gB[(h*28+16+p*3+0)*NRES + n] = gx;
        g_gB[(h*28+16+p*3+1)*NRES + n] = gy;
        g_gB[(h*28+16+p*3+2)*NRES + n] = gz;
        kgs[u*3+0] = gx; kgs[u*3+1] = gy; kgs[u*3+2] = gz;
    } else {
        const int u = t - 96;
        const float* src = row + 864 + u*3;
        float* dst = g_vg + n*288 + u*3;
        const float p0 = src[0], p1 = src[1], p2 = src[2];
        dst[0] = fmaf(R[0],p0, fmaf(R[1],p1, fmaf(R[2],p2, T[0])));
        dst[1] = fmaf(R[3],p0, fmaf(R[4],p1, fmaf(R[5],p2, T[1])));
        dst[2] = fmaf(R[6],p0, fmaf(R[7],p1, fmaf(R[8],p2, T[2])));
    }
    {
        const int h = t >> 4, c = t & 15;
        g_gA[(h*28+c)*NRES + n] = 0.25f * row[h*16 + c];
        g_gB[(h*28+c)*NRES + n] = row[192 + h*16 + c];
    }
    __syncthreads();
    if (t < 12) {
        float s2 = 0.f;
#pragma unroll
        for (int j = 0; j < 12; j++) s2 = fmaf(kgs[t*12+j], kgs[t*12+j], s2);
        g_gC[t*NRES + n] = -0.5f * hw[t] * s2;
    }
}

// ---------------- pair bias stream: 2 head-groups x 6 heads, c-split pairs ----------------
#define PB_WBT 0        // 1536
#define PB_EMB 1536     // 768
#define PB_PH  2304     // 36
#define PB_BB  2340     // 12
#define PB_TN  2352     // 4
#define PB_TM0 2356     // 192
#define PB_TM1 2548     // 192
#define PB_RED 2740     // 768
#define PB_Z0  3508     // 8448
#define PB_Z1  11956    // 8448
#define PB_END 20404    // 81616 B
__global__ void k_pairbias(const float* __restrict__ z, const float* __restrict__ trans,
                           const float* __restrict__ Wb, const float* __restrict__ bb,
                           const float* __restrict__ emb, const float* __restrict__ sl)
{
    extern __shared__ float sm[];
    const int n = blockIdx.x, tid = threadIdx.x;  // 256 thr

    auto pf = [&](int buf, int mc) {
        const float4* zsrc = (const float4*)(z + ((size_t)n * NRES + mc*64) * CZ);
        float* zb = sm + (buf ? PB_Z1 : PB_Z0);
        for (int i = tid; i < 2048; i += 256)
            cpa16(zb + (i >> 5)*132 + (i & 31)*4, zsrc + i);
        if (tid < 48)
            cpa16(sm + (buf ? PB_TM1 : PB_TM0) + tid*4, trans + mc*192 + tid*4);
    };
    pf(0, 0); CP_COMMIT();
    pf(1, 1); CP_COMMIT();

    for (int i = tid; i < 1536; i += 256) {
        const int h = i >> 7, c = i & 127;
        sm[PB_WBT + i] = Wb[c*NH + h];
    }
    for (int i = tid; i < 768; i += 256) sm[PB_EMB + i] = emb[i];
    if (tid < 12) {
        sm[PB_BB + tid] = bb[tid];
        const float e0 = expf(sl[tid]), e1 = expf(sl[12+tid]), e2 = expf(sl[24+tid]);
        const float inv = 1.0f / (e0 + e1 + e2);
        sm[PB_PH + tid] = e0*inv; sm[PB_PH + 12 + tid] = e1*inv; sm[PB_PH + 24 + tid] = e2*inv;
    }
    if (tid < 3) sm[PB_TN + tid] = trans[n*3 + tid];

    const int hg = tid >> 7;            // 0..1 (6 heads each)
    const int cs = (tid >> 6) & 1;      // c4 split
    const int ml = tid & 63;
    const int hb = hg * 6;

    for (int mc = 0; mc < 8; mc++) {
        if (mc < 7) CP_WAIT1(); else CP_WAIT0();
        __syncthreads();
        const int buf = mc & 1;
        const float4* zr = (const float4*)(sm + (buf ? PB_Z1 : PB_Z0) + ml*132) + cs*16;
        const float* tm = sm + (buf ? PB_TM1 : PB_TM0);

        float a[6][4];
#pragma unroll
        for (int j = 0; j < 6; j++) { a[j][0]=0.f; a[j][1]=0.f; a[j][2]=0.f; a[j][3]=0.f; }
#pragma unroll 4
        for (int c4 = 0; c4 < 16; c4++) {
            const float4 zv = zr[c4];
#pragma unroll
            for (int j = 0; j < 6; j++) {
                const float4 w = ((const float4*)(sm + PB_WBT + (hb+j)*128))[cs*16 + c4];
                a[j][0] = fmaf(zv.x, w.x, a[j][0]);
                a[j][1] = fmaf(zv.y, w.y, a[j][1]);
                a[j][2] = fmaf(zv.z, w.z, a[j][2]);
                a[j][3] = fmaf(zv.w, w.w, a[j][3]);
            }
        }
        float p[6];
#pragma unroll
        for (int j = 0; j < 6; j++) p[j] = (a[j][0]+a[j][1]) + (a[j][2]+a[j][3]);
        if (cs == 1) {
#pragma unroll
            for (int j = 0; j < 6; j++) sm[PB_RED + hg*384 + ml*6 + j] = p[j];
        }
        __syncthreads();
        if (cs == 0) {
            const float dx = sm[PB_TN+0] - tm[ml*3+0];
            const float dy = sm[PB_TN+1] - tm[ml*3+1];
            const float dz = sm[PB_TN+2] - tm[ml*3+2];
            const float dist = __fsqrt_rn(fmaf(dx,dx, fmaf(dy,dy, dz*dz)));
            int bin = (int)ceilf(dist * 2.0f) - 1;
            bin = max(0, min(63, bin));
            const int msrow = (dist <= 5.0f) ? 0 : (dist <= 15.0f) ? 12 : -1;
            const int m = mc*64 + ml;
#pragma unroll
            for (int j = 0; j < 6; j++) {
                const int h = hb + j;
                float v = sm[PB_BB + h] + p[j] + sm[PB_RED + hg*384 + ml*6 + j];
                v += sm[PB_EMB + bin*12 + h] + sm[PB_PH + 24 + h];
                if (msrow >= 0) v += sm[PB_PH + msrow + h];
                g_attn[(size_t)h*N2 + (size_t)n*NRES + m] = v;
            }
        }
        __syncthreads();
        if (mc + 2 < 8) { pf(buf, mc + 2); CP_COMMIT(); }
    }
}

// ---------------- fused geometry GEMM + softmax (conflict-free interleaved map) --
// block = (16 n, 1 head, all m=512); thread (nl, mg): acc j <-> float4 m-index j*16+mg
#define GS_A 0        // 448
#define GS_C 448      // 512
#define GS_B 960      // 14336
#define GS_END 15296  // 61184 B
__global__ void k_geosm()
{
    extern __shared__ float sm[];
    const int h = blockIdx.y;
    const int n0 = blockIdx.x * 16;
    const int tid = threadIdx.x;      // 256
    const int nl = tid >> 4, mg = tid & 15;

    for (int i = tid; i < 448; i += 256) {
        const int c = i >> 4, r = i & 15;
        sm[GS_A + c*16 + r] = g_gA[(size_t)(h*28+c)*NRES + n0 + r];
    }
    for (int i = tid; i < 128; i += 256)
        *(float4*)(sm + GS_C + i*4) = *(const float4*)(g_gC + h*NRES + i*4);
    for (int i = tid; i < 3584; i += 256) {
        const int c = i >> 7, mq = i & 127;
        *(float4*)(sm + GS_B + c*512 + mq*4) =
            *(const float4*)(g_gB + (size_t)(h*28+c)*NRES + mq*4);
    }
    __syncthreads();

    float acc[32];
#pragma unroll
    for (int j = 0; j < 32; j++) acc[j] = 0.f;

#pragma unroll 4
    for (int c = 0; c < 28; c++) {
        const float a = sm[GS_A + c*16 + nl];
        const float4* b4 = (const float4*)(sm + GS_B + c*512);
#pragma unroll
        for (int j = 0; j < 8; j++) {
            const float4 b = b4[j*16 + mg];        // lanes -> consecutive float4s
            acc[j*4+0] = fmaf(a, b.x, acc[j*4+0]);
            acc[j*4+1] = fmaf(a, b.y, acc[j*4+1]);
            acc[j*4+2] = fmaf(a, b.z, acc[j*4+2]);
            acc[j*4+3] = fmaf(a, b.w, acc[j*4+3]);
        }
    }

    float4* arow = (float4*)(g_attn + (size_t)h*N2 + (size_t)(n0+nl)*NRES);
    const float4* cv4 = (const float4*)(sm + GS_C);
    float mx = -1e30f;
#pragma unroll
    for (int j = 0; j < 8; j++) {
        const int idx = j*16 + mg;
        const float4 bias = arow[idx];
        const float4 cv = cv4[idx];
        acc[j*4+0] += bias.x + cv.x;
        acc[j*4+1] += bias.y + cv.y;
        acc[j*4+2] += bias.z + cv.z;
        acc[j*4+3] += bias.w + cv.w;
        mx = fmaxf(mx, fmaxf(fmaxf(acc[j*4+0], acc[j*4+1]), fmaxf(acc[j*4+2], acc[j*4+3])));
    }
    // same-n threads form one 16-lane half-warp (lane = (nl&1)*16 + mg)
#pragma unroll
    for (int o = 8; o; o >>= 1) mx = fmaxf(mx, __shfl_xor_sync(0xffffffffu, mx, o));
    float sum = 0.f;
#pragma unroll
    for (int j = 0; j < 32; j++) { acc[j] = __expf(acc[j] - mx); sum += acc[j]; }
#pragma unroll
    for (int o = 8; o; o >>= 1) sum += __shfl_xor_sync(0xffffffffu, sum, o);
    const float inv = 1.0f / sum;
#pragma unroll
    for (int j = 0; j < 8; j++) {
        const int idx = j*16 + mg;
        arow[idx] = make_float4(acc[j*4+0]*inv, acc[j*4+1]*inv, acc[j*4+2]*inv, acc[j*4+3]*inv);
    }
}

// ---------------- pair_feat: warp = (head-group of 4, m-slice), 1 z-LDS per 16 FMA ----
#define PF_Z0 0       // 4096
#define PF_Z1 4096    // 4096
#define PF_A0 8192    // 384
#define PF_A1 8576    // 384
#define PF_PF 8960    // 1536
#define PF_END 10496  // 41984 B
__global__ void k_pairfeat(const float* __restrict__ z)
{
    extern __shared__ float sm[];
    const int n = blockIdx.x, tid = threadIdx.x;  // 384 thr = 12 warps
    const int wid = tid >> 5, lane = tid & 31;
    const int hg = wid >> 2;          // 0..2 (4 heads each)
    const int ms = wid & 3;           // m-slice

    const float4* zsrc = (const float4*)(z + (size_t)n * NRES * CZ);

    auto pfl = [&](int buf, int mc) {
        float* zb = sm + (buf ? PF_Z1 : PF_Z0);
        for (int i = tid; i < 1024; i += 384)
            cpa16(zb + i*4, zsrc + mc*1024 + i);
        {
            const int h = tid >> 5, mm = tid & 31;
            cpa4(sm + (buf ? PF_A1 : PF_A0) + h*32 + mm,
                 g_attn + (size_t)h*N2 + (size_t)n*NRES + mc*32 + mm);
        }
    };
    pfl(0, 0); CP_COMMIT();
    pfl(1, 1); CP_COMMIT();

    float acc[4][4];
#pragma unroll
    for (int i = 0; i < 4; i++)
#pragma unroll
        for (int j = 0; j < 4; j++) acc[i][j] = 0.f;

    for (int mc = 0; mc < 16; mc++) {
        if (mc < 15) CP_WAIT1(); else CP_WAIT0();
        __syncthreads();
        const int buf = mc & 1;
        const float* zc = sm + (buf ? PF_Z1 : PF_Z0);
        const float* ac = sm + (buf ? PF_A1 : PF_A0);
#pragma unroll
        for (int j = 0; j < 8; j++) {
            const int m = ms*8 + j;
            const float4 zv = *(const float4*)(zc + m*128 + lane*4);
            const float w0 = ac[(hg*4+0)*32 + m];
            const float w1 = ac[(hg*4+1)*32 + m];
            const float w2 = ac[(hg*4+2)*32 + m];
            const float w3 = ac[(hg*4+3)*32 + m];
            acc[0][0]=fmaf(w0,zv.x,acc[0][0]); acc[0][1]=fmaf(w0,zv.y,acc[0][1]);
            acc[0][2]=fmaf(w0,zv.z,acc[0][2]); acc[0][3]=fmaf(w0,zv.w,acc[0][3]);
            acc[1][0]=fmaf(w1,zv.x,acc[1][0]); acc[1][1]=fmaf(w1,zv.y,acc[1][1]);
            acc[1][2]=fmaf(w1,zv.z,acc[1][2]); acc[1][3]=fmaf(w1,zv.w,acc[1][3]);
            acc[2][0]=fmaf(w2,zv.x,acc[2][0]); acc[2][1]=fmaf(w2,zv.y,acc[2][1]);
            acc[2][2]=fmaf(w2,zv.z,acc[2][2]); acc[2][3]=fmaf(w2,zv.w,acc[2][3]);
            acc[3][0]=fmaf(w3,zv.x,acc[3][0]); acc[3][1]=fmaf(w3,zv.y,acc[3][1]);
            acc[3][2]=fmaf(w3,zv.z,acc[3][2]); acc[3][3]=fmaf(w3,zv.w,acc[3][3]);
        }
        __syncthreads();
        if (mc + 2 < 16) { pfl(buf, mc + 2); CP_COMMIT(); }
    }

    float4* pf4 = (float4*)(sm + PF_PF);
#pragma unroll
    for (int r = 0; r < 4; r++) {
        if (ms == r) {
#pragma unroll
            for (int hh = 0; hh < 4; hh++) {
                const int fi = (hg*4 + hh)*32 + lane;
                if (r == 0) {
                    pf4[fi] = make_float4(acc[hh][0], acc[hh][1], acc[hh][2], acc[hh][3]);
                } else {
                    float4 v = pf4[fi];
                    v.x += acc[hh][0]; v.y += acc[hh][1];
                    v.z += acc[hh][2]; v.w += acc[hh][3];
                    pf4[fi] = v;
                }
            }
        }
        __syncthreads();
    }
    {
        const int h = tid >> 5, cq = tid & 31;
        *(float4*)(g_feats + (size_t)n*OUTD + h*HF + 48 + cq*4) = pf4[tid];
    }
}

// ---------------- out_scalar + out_pts(local) + norms; 4 n per block ----------------
#define OV_AT 0        // 12*128 [h][m][ni]
#define OV_V  1536     // 6144
#define OV_VG 7680     // 9216
#define OV_PG 16896    // 4*288
#define OV_END 18048
__global__ void k_outv(const float* __restrict__ rot, const float* __restrict__ trans)
{
    extern __shared__ float sm[];
    const int n0 = blockIdx.x * 4, tid = threadIdx.x;  // 480 thr, grid 128
    float acc0=0.f, acc1=0.f, acc2=0.f, acc3=0.f;

    for (int mc = 0; mc < 16; mc++) {
        const int m0 = mc * 32;
        __syncthreads();
        for (int i = tid; i < 1536; i += 480) {
            const int hh = i >> 7, r = i & 127;
            const int ni = r >> 5, mm = r & 31;
            sm[OV_AT + hh*128 + mm*4 + ni] =
                g_attn[(size_t)hh*N2 + (size_t)(n0+ni)*NRES + m0 + mm];
        }
        for (int i = tid; i < 1536; i += 480) {
            const int mm = i / 48, q = i - mm*48;
            cpa16(sm + OV_V + mm*192 + q*4, g_proj + (size_t)(m0+mm)*PROJW + 384 + q*4);
        }
        for (int i = tid; i < 2304; i += 480)
            cpa16(sm + OV_VG + i*4, g_vg + m0*288 + i*4);
        CP_COMMIT(); CP_WAIT0();
        __syncthreads();

        if (tid < 192) {
            const int hh = tid >> 4, c = tid & 15;
            const float* vs = sm + OV_V + hh*16 + c;
            const float4* at4 = (const float4*)(sm + OV_AT + hh*128);
#pragma unroll
            for (int mm = 0; mm < 32; mm++) {
                const float4 w = at4[mm];
                const float vv = vs[mm*192];
                acc0 = fmaf(w.x, vv, acc0);
                acc1 = fmaf(w.y, vv, acc1);
                acc2 = fmaf(w.z, vv, acc2);
                acc3 = fmaf(w.w, vv, acc3);
            }
        } else {
            const int idx = tid - 192, hh = idx / 24, u = idx - hh*24;
            const float* vs = sm + OV_VG + hh*24 + u;
            const float4* at4 = (const float4*)(sm + OV_AT + hh*128);
#pragma unroll
            for (int mm = 0; mm < 32; mm++) {
                const float4 w = at4[mm];
                const float vv = vs[mm*288];
                acc0 = fmaf(w.x, vv, acc0);
                acc1 = fmaf(w.y, vv, acc1);
                acc2 = fmaf(w.z, vv, acc2);
                acc3 = fmaf(w.w, vv, acc3);
            }
        }
    }
    __syncthreads();
    if (tid < 192) {
        const int hh = tid >> 4, c = tid & 15;
        g_feats[(size_t)(n0+0)*OUTD + hh*HF + c] = acc0;
        g_feats[(size_t)(n0+1)*OUTD + hh*HF + c] = acc1;
        g_feats[(size_t)(n0+2)*OUTD + hh*HF + c] = acc2;
        g_feats[(size_t)(n0+3)*OUTD + hh*HF + c] = acc3;
    } else {
        const int idx = tid - 192;
        sm[OV_PG + 0*288 + idx] = acc0;
        sm[OV_PG + 1*288 + idx] = acc1;
        sm[OV_PG + 2*288 + idx] = acc2;
        sm[OV_PG + 3*288 + idx] = acc3;
    }
    __syncthreads();
    if (tid < 384) {
        const int ni = tid / 96, r = tid - ni*96;
        const int hh = r / 8, p = r - hh*8;
        const int n = n0 + ni;
        float R[9];
#pragma unroll
        for (int i = 0; i < 9; i++) R[i] = rot[n*9 + i];
        const float gx = sm[OV_PG + ni*288 + hh*24 + p*3 + 0] - trans[n*3 + 0];
        const float gy = sm[OV_PG + ni*288 + hh*24 + p*3 + 1] - trans[n*3 + 1];
        const float gz = sm[OV_PG + ni*288 + hh*24 + p*3 + 2] - trans[n*3 + 2];
        const float lx = fmaf(R[0],gx, fmaf(R[3],gy, R[6]*gz));
        const float ly = fmaf(R[1],gx, fmaf(R[4],gy, R[7]*gz));
        const float lz = fmaf(R[2],gx, fmaf(R[5],gy, R[8]*gz));
        float* f = g_feats + (size_t)n*OUTD + hh*HF;
        f[16 + p*3 + 0] = lx; f[16 + p*3 + 1] = ly; f[16 + p*3 + 2] = lz;
        f[40 + p] = __fsqrt_rn(fmaf(lx,lx, fmaf(ly,ly, lz*lz)));
    }
}

// ---------------- selective-K GEMM over per-head column ranges (+row base) ------
__global__ void k_sgemm_sel(const float* __restrict__ A, const float* __restrict__ B,
                            float* __restrict__ C, int pbase, int kbase, int klen, int mbase)
{
    __shared__ alignas(16) float As[16][64];
    __shared__ alignas(16) float Bs[16][64];
    const int tid = threadIdx.x;
    const int tx = tid & 15, ty = tid >> 4;
    const int bm = (mbase + blockIdx.y) * 64, bn = blockIdx.x * 64;
    const int hb = blockIdx.z * 3;
    C += (size_t)(pbase + blockIdx.z) * NRES * CS;

    const int am  = tid >> 2, akq = tid & 3;
    const int bkk = tid >> 4, bn4 = tid & 15;

    float acc[4][4];
#pragma unroll
    for (int i = 0; i < 4; i++)
#pragma unroll
        for (int j = 0; j < 4; j++) acc[i][j] = 0.f;

    for (int hh = hb; hh < hb + 3; hh++) {
        const int kc0 = hh * HF + kbase;
        for (int kt = 0; kt < klen; kt += 16) {
            const int kc = kc0 + kt;
            float4 av = *(const float4*)(A + (size_t)(bm + am) * OUTD + kc + akq * 4);
            As[akq*4+0][am] = av.x; As[akq*4+1][am] = av.y;
            As[akq*4+2][am] = av.z; As[akq*4+3][am] = av.w;
            float4 bv = *(const float4*)(B + (size_t)(kc + bkk) * CS + bn + bn4 * 4);
            *(float4*)&Bs[bkk][bn4*4] = bv;
            __syncthreads();
#pragma unroll
            for (int kk = 0; kk < 16; kk++) {
                float4 a = *(const float4*)&As[kk][ty*4];
                float4 b = *(const float4*)&Bs[kk][tx*4];
                acc[0][0]=fmaf(a.x,b.x,acc[0][0]); acc[0][1]=fmaf(a.x,b.y,acc[0][1]);
                acc[0][2]=fmaf(a.x,b.z,acc[0][2]); acc[0][3]=fmaf(a.x,b.w,acc[0][3]);
                acc[1][0]=fmaf(a.y,b.x,acc[1][0]); acc[1][1]=fmaf(a.y,b.y,acc[1][1]);
                acc[1][2]=fmaf(a.y,b.z,acc[1][2]); acc[1][3]=fmaf(a.y,b.w,acc[1][3]);
                acc[2][0]=fmaf(a.z,b.x,acc[2][0]); acc[2][1]=fmaf(a.z,b.y,acc[2][1]);
                acc[2][2]=fmaf(a.z,b.z,acc[2][2]); acc[2][3]=fmaf(a.z,b.w,acc[2][3]);
                acc[3][0]=fmaf(a.w,b.x,acc[3][0]); acc[3][1]=fmaf(a.w,b.y,acc[3][1]);
                acc[3][2]=fmaf(a.w,b.z,acc[3][2]); acc[3][3]=fmaf(a.w,b.w,acc[3][3]);
            }
            __syncthreads();
        }
    }
#pragma unroll
    for (int i = 0; i < 4; i++) {
        const int row = bm + ty * 4 + i;
#pragma unroll
        for (int j = 0; j < 4; j++)
            C[(size_t)row * CS + bn + tx * 4 + j] = acc[i][j];
    }
}

// ---------------- reduce 8 partials + bias ----------------
__global__ void k_reduce(const float* __restrict__ bout, float* __restrict__ out)
{
    const int i = blockIdx.x * 256 + threadIdx.x;
    const int NE = NRES * CS;
    float v = 0.f;
#pragma unroll
    for (int p = 0; p < 8; p++) v += g_part[(size_t)p*NE + i];
    out[i] = v + bout[i % CS];
}

// ---------------- launch ----------------
static float* symaddr(const void* sym) {
    void* p = nullptr;
    cudaGetSymbolAddress(&p, sym);
    return (float*)p;
}

extern "C" void kernel_launch(void* const* d_in, const int* in_sizes, int n_in,
                              void* d_out, int out_size) {
    const float* s     = (const float*)d_in[0];
    const float* z     = (const float*)d_in[1];
    const float* trans = (const float*)d_in[2];
    const float* rot   = (const float*)d_in[3];
    const float* Wq    = (const float*)d_in[4];
    const float* bq    = (const float*)d_in[5];
    const float* Wk    = (const float*)d_in[6];
    const float* bk    = (const float*)d_in[7];
    const float* Wv    = (const float*)d_in[8];
    const float* bv    = (const float*)d_in[9];
    const float* Wqp   = (const float*)d_in[10];
    const float* bqp   = (const float*)d_in[11];
    const float* Wkp   = (const float*)d_in[12];
    const float* bkp   = (const float*)d_in[13];
    const float* Wvp   = (const float*)d_in[14];
    const float* bvp   = (const float*)d_in[15];
    const float* Wb    = (const float*)d_in[16];
    const float* bb    = (const float*)d_in[17];
    const float* emb   = (const float*)d_in[18];
    const float* sl    = (const float*)d_in[19];
    const float* hw    = (const float*)d_in[20];
    const float* Wout  = (const float*)d_in[21];
    const float* bout  = (const float*)d_in[22];
    float* out = (float*)d_out;

    float* pf = symaddr(g_feats);
    float* pp = symaddr(g_part);

    static cudaStream_t s2 = nullptr;
    static cudaEvent_t evFork = nullptr, evZ = nullptr, evS = nullptr, evPF = nullptr, evP = nullptr;
    if (!s2) {
        cudaStreamCreateWithFlags(&s2, cudaStreamNonBlocking);
        cudaEventCreateWithFlags(&evFork, cudaEventDisableTiming);
        cudaEventCreateWithFlags(&evZ,    cudaEventDisableTiming);
        cudaEventCreateWithFlags(&evS,    cudaEventDisableTiming);
        cudaEventCreateWithFlags(&evPF,   cudaEventDisableTiming);
        cudaEventCreateWithFlags(&evP,    cudaEventDisableTiming);
        cudaFuncSetAttribute(k_pairbias, cudaFuncAttributeMaxDynamicSharedMemorySize, PB_END * (int)sizeof(float));
        cudaFuncSetAttribute(k_geosm,    cudaFuncAttributeMaxDynamicSharedMemorySize, GS_END * (int)sizeof(float));
        cudaFuncSetAttribute(k_pairfeat, cudaFuncAttributeMaxDynamicSharedMemorySize, PF_END * (int)sizeof(float));
        cudaFuncSetAttribute(k_outv,     cudaFuncAttributeMaxDynamicSharedMemorySize, OV_END * (int)sizeof(float));
    }

    // fork1: z-path (pairbias) on s2 concurrent with s-path (proj->prep) on default
    cudaEventRecord(evFork, 0);
    cudaStreamWaitEvent(s2, evFork, 0);
    k_pairbias<<<NRES, 256, PB_END * sizeof(float), s2>>>(z, trans, Wb, bb, emb, sl);
    cudaEventRecord(evZ, s2);

    k_proj<<<dim3(18,8,1), 256>>>(s, Wq,bq, Wk,bk, Wv,bv, Wqp,bqp, Wkp,bkp, Wvp,bvp);
    k_prep<<<NRES, 192>>>(rot, trans, hw);

    // join: geosm RMWs attn (needs pairbias) and reads prep outputs; includes softmax
    cudaStreamWaitEvent(0, evZ, 0);
    k_geosm<<<dim3(32,12,1), 256, GS_END * sizeof(float)>>>();
    cudaEventRecord(evS, 0);

    // fork2: pairfeat + 6/8 of gemmB on s2; outv + gemmA + 2/8 of gemmB on default
    cudaStreamWaitEvent(s2, evS, 0);
    k_pairfeat<<<NRES, 384, PF_END * sizeof(float), s2>>>(z);
    cudaEventRecord(evPF, s2);
    k_sgemm_sel<<<dim3(6,6,4), 256, 0, s2>>>(pf, Wout, pp, 4, 48, 128, 0);  // rows 0-5
    cudaEventRecord(evP, s2);

    k_outv<<<128, 480, OV_END * sizeof(float)>>>(rot, trans);
    k_sgemm_sel<<<dim3(6,8,4), 256>>>(pf, Wout, pp, 0, 0, 48, 0);           // gemmA
    cudaStreamWaitEvent(0, evPF, 0);
    k_sgemm_sel<<<dim3(6,2,4), 256>>>(pf, Wout, pp, 4, 48, 128, 6);         // rows 6-7

    // join before reduce (needs all 8 partials)
    cudaStreamWaitEvent(0, evP, 0);
    k_reduce<<<(NRES*CS)/256, 256>>>(bout, out);
}